// round 15
// baseline (speedup 1.0000x reference)
#include <cuda_runtime.h>
#include <cuda_bf16.h>
#include <math.h>
#include <stdint.h>

// ---------------- problem constants ----------------
#define Bn   64
#define Qn   64
#define Tn   448
#define Dn   512
#define FDn  1024
#define Hn   8
#define NLn  2
#define FFn  2048
#define Sn   512
#define DHn  64
#define BSr  (Bn*Sn)
#define BTr  (Bn*Tn)

// ---------------- scratch ----------------
__device__ float g_x [BSr*Dn];
__device__ float g_t1[BSr*Dn];
__device__ __nv_bfloat16 g_xh [BSr*Dn],  g_xl [BSr*Dn];
__device__ __nv_bfloat16 g_aqh[BSr*Dn],  g_aql[BSr*Dn];
__device__ __nv_bfloat16 g_akh[BSr*Dn],  g_akl[BSr*Dn];
__device__ __nv_bfloat16 g_avh[BSr*Dn],  g_avl[BSr*Dn];
__device__ __nv_bfloat16 g_ch [BSr*Dn],  g_cl [BSr*Dn];
__device__ __nv_bfloat16 g_hh [BSr*FFn], g_hl [BSr*FFn];
__device__ __nv_bfloat16 g_vh [BTr*FDn], g_vl [BTr*FDn];
__device__ __nv_bfloat16 g_wvh [FDn*Dn],        g_wvl [FDn*Dn];
__device__ __nv_bfloat16 g_wqkvh[NLn*3*Dn*Dn],  g_wqkvl[NLn*3*Dn*Dn];
__device__ __nv_bfloat16 g_woh [NLn*Dn*Dn],     g_wol [NLn*Dn*Dn];
__device__ __nv_bfloat16 g_w1h [NLn*Dn*FFn],    g_w1l [NLn*Dn*FFn];
__device__ __nv_bfloat16 g_w2h [NLn*FFn*Dn],    g_w2l [NLn*FFn*Dn];

// ---------------- helpers ----------------
__device__ __forceinline__ uint32_t smem_u32(const void* p) {
    uint32_t a;
    asm("{ .reg .u64 t; cvta.to.shared.u64 t, %1; cvt.u32.u64 %0, t; }" : "=r"(a) : "l"(p));
    return a;
}
__device__ __forceinline__ void split_bf16(float x, __nv_bfloat16& h, __nv_bfloat16& l) {
    h = __float2bfloat16_rn(x);
    l = __float2bfloat16_rn(x - __bfloat162float(h));
}
__device__ __forceinline__ uint32_t pack2(__nv_bfloat16 a, __nv_bfloat16 b) {
    __nv_bfloat162 v(a, b);
    return *reinterpret_cast<uint32_t*>(&v);
}
__device__ __forceinline__ void pack_split2(float a, float b, uint32_t& hi, uint32_t& lo) {
    __nv_bfloat16 ha, la, hb, lb;
    split_bf16(a, ha, la);
    split_bf16(b, hb, lb);
    hi = pack2(ha, hb);
    lo = pack2(la, lb);
}
__device__ __forceinline__ void ldsm_x4(uint32_t& r0, uint32_t& r1, uint32_t& r2, uint32_t& r3,
                                        uint32_t addr) {
    asm volatile("ldmatrix.sync.aligned.m8n8.x4.shared.b16 {%0,%1,%2,%3}, [%4];"
                 : "=r"(r0), "=r"(r1), "=r"(r2), "=r"(r3) : "r"(addr));
}
__device__ __forceinline__ void ldsm_x4t(uint32_t& r0, uint32_t& r1, uint32_t& r2, uint32_t& r3,
                                         uint32_t addr) {
    asm volatile("ldmatrix.sync.aligned.m8n8.x4.trans.shared.b16 {%0,%1,%2,%3}, [%4];"
                 : "=r"(r0), "=r"(r1), "=r"(r2), "=r"(r3) : "r"(addr));
}
__device__ __forceinline__ void mma16816(float* d, const uint32_t* a, const uint32_t* b) {
    asm volatile(
        "mma.sync.aligned.m16n8k16.row.col.f32.bf16.bf16.f32 "
        "{%0,%1,%2,%3}, {%4,%5,%6,%7}, {%8,%9}, {%0,%1,%2,%3};"
        : "+f"(d[0]), "+f"(d[1]), "+f"(d[2]), "+f"(d[3])
        : "r"(a[0]), "r"(a[1]), "r"(a[2]), "r"(a[3]), "r"(b[0]), "r"(b[1]));
}
__device__ __forceinline__ void cp16(uint32_t s, const void* g) {
    asm volatile("cp.async.cg.shared.global [%0], [%1], 16;" :: "r"(s), "l"(g));
}
#define CP_COMMIT() asm volatile("cp.async.commit_group;" ::: "memory")
#define CP_WAIT0()  asm volatile("cp.async.wait_group 0;" ::: "memory")
#define CP_WAIT1()  asm volatile("cp.async.wait_group 1;" ::: "memory")

__device__ __forceinline__ float fexp2(float y) {
    y = fmaxf(y, -126.f);
    float n = rintf(y);
    float r = y - n;
    float p = fmaf(1.333356e-3f, r, 9.618129e-3f);
    p = fmaf(p, r, 5.5504109e-2f);
    p = fmaf(p, r, 2.40226507e-1f);
    p = fmaf(p, r, 6.93147181e-1f);
    p = fmaf(p, r, 1.0f);
    return p * __int_as_float(((int)n + 127) << 23);
}

// ---------------- GEMM smem layout: 128x128 tile, BK=32, 3-stage ----------------
#define ASTRIDE 40
#define BSTRIDE 136
#define STG_A   (128 * ASTRIDE * 2)
#define STG_B   (32 * BSTRIDE * 2)
#define STAGE_BYTES (2 * STG_A + 2 * STG_B)
#define NSTAGE  3
#define SM_TOTAL (NSTAGE * STAGE_BYTES)      // 113664 -> 2 CTAs/SM

__device__ __forceinline__ void gemm_compute(uint32_t sbase, uint32_t a_off, int warp_n, int lane,
                                             float (&acc)[2][8][4])
{
#pragma unroll
    for (int ks = 0; ks < 2; ks++) {
        uint32_t ah[2][4], al[2][4];
#pragma unroll
        for (int mt = 0; mt < 2; mt++) {
            uint32_t aa = sbase + a_off + (uint32_t)(mt * 16 * ASTRIDE) * 2 + ks * 32;
            ldsm_x4(ah[mt][0], ah[mt][1], ah[mt][2], ah[mt][3], aa);
            ldsm_x4(al[mt][0], al[mt][1], al[mt][2], al[mt][3], aa + STG_A);
        }
#pragma unroll
        for (int ntp = 0; ntp < 4; ntp++) {
            uint32_t boff = sbase + 2 * STG_A +
                (uint32_t)((ks * 16 + (lane & 15)) * BSTRIDE
                           + warp_n * 64 + ntp * 16 + ((lane >> 4) & 1) * 8) * 2;
            uint32_t bh[4], bl[4];
            ldsm_x4t(bh[0], bh[1], bh[2], bh[3], boff);
            ldsm_x4t(bl[0], bl[1], bl[2], bl[3], boff + STG_B);
#pragma unroll
            for (int mt = 0; mt < 2; mt++) {
                mma16816(acc[mt][2 * ntp],     ah[mt], bh);
                mma16816(acc[mt][2 * ntp],     ah[mt], bl);
                mma16816(acc[mt][2 * ntp],     al[mt], bh);
                mma16816(acc[mt][2 * ntp + 1], ah[mt], bh + 2);
                mma16816(acc[mt][2 * ntp + 1], ah[mt], bl + 2);
                mma16816(acc[mt][2 * ntp + 1], al[mt], bh + 2);
            }
        }
    }
}

// ---- shared GEMM body: CTA tile 128x128 at (row0, col0); A/B pre-offset ----
template<int EPI, int OUT>
__device__ __forceinline__ void gemm_body(
    const __nv_bfloat16* __restrict__ Agh, const __nv_bfloat16* __restrict__ Agl,
    const __nv_bfloat16* __restrict__ Bgh, const __nv_bfloat16* __restrict__ Bgl,
    const float* __restrict__ bias, const float* __restrict__ R,
    float* __restrict__ C, __nv_bfloat16* __restrict__ Ch, __nv_bfloat16* __restrict__ Cl,
    int N, int K, int row0g, int col0g)
{
    extern __shared__ char smem[];
    const uint32_t sb = smem_u32(smem);
    const int tid = threadIdx.x, wid = tid >> 5, lane = tid & 31;
    const int warp_m = wid & 3, warp_n = wid >> 2;
    const int gid = lane >> 2, tig = lane & 3;
    const int a_row = tid >> 2, a_seg = tid & 3;
    const int b_row = tid >> 4, b_seg = tid & 15;

    float acc[2][8][4];
#pragma unroll
    for (int mt = 0; mt < 2; mt++)
#pragma unroll
        for (int nt = 0; nt < 8; nt++)
#pragma unroll
            for (int e = 0; e < 4; e++) acc[mt][nt][e] = 0.f;

    const uint32_t a_off = (uint32_t)((warp_m * 32 + (lane & 15)) * ASTRIDE + (lane >> 4) * 8) * 2;
    const int nch = K >> 5;

#define LOAD_STAGE(slot, kc) do { \
    const uint32_t sbase_ = sb + (slot) * STAGE_BYTES; \
    _Pragma("unroll") \
    for (int i = 0; i < 2; i++) { \
        int row = a_row + i * 64; \
        uint32_t so = sbase_ + (uint32_t)(row * ASTRIDE + a_seg * 8) * 2; \
        size_t go = (size_t)row * K + (kc) * 32 + a_seg * 8; \
        cp16(so, Agh + go); \
        cp16(so + STG_A, Agl + go); \
    } \
    _Pragma("unroll") \
    for (int i = 0; i < 2; i++) { \
        int kk = b_row + i * 16; \
        uint32_t so = sbase_ + 2 * STG_A + (uint32_t)(kk * BSTRIDE + b_seg * 8) * 2; \
        size_t go = (size_t)((kc) * 32 + kk) * N + b_seg * 8; \
        cp16(so, Bgh + go); \
        cp16(so + STG_B, Bgl + go); \
    } \
} while (0)

    LOAD_STAGE(0, 0); CP_COMMIT();
    LOAD_STAGE(1, 1); CP_COMMIT();

    for (int kc = 0; kc < nch; kc++) {
        CP_WAIT1();
        __syncthreads();
        const int nk = kc + 2;
        if (nk < nch) { LOAD_STAGE(nk % NSTAGE, nk); }
        CP_COMMIT();
        gemm_compute(sb + (kc % NSTAGE) * STAGE_BYTES, a_off, warp_n, lane, acc);
    }
#undef LOAD_STAGE

#pragma unroll
    for (int nt = 0; nt < 8; nt++) {
        const int col = col0g + warp_n * 64 + nt * 8 + 2 * tig;
        const float2 bs = *(const float2*)(bias + col);
#pragma unroll
        for (int mt = 0; mt < 2; mt++) {
            const int row0 = row0g + warp_m * 32 + mt * 16 + gid;
#pragma unroll
            for (int half = 0; half < 2; half++) {
                const int row = row0 + half * 8;
                const size_t off = (size_t)row * N + col;
                float v0 = acc[mt][nt][half * 2 + 0] + bs.x;
                float v1 = acc[mt][nt][half * 2 + 1] + bs.y;
                if (EPI == 1) {
                    v0 = 0.5f * v0 * (1.f + erff(v0 * 0.70710678118654752f));
                    v1 = 0.5f * v1 * (1.f + erff(v1 * 0.70710678118654752f));
                } else if (EPI == 2) {
                    float2 rr = *(const float2*)(R + off);
                    v0 += rr.x; v1 += rr.y;
                }
                if (OUT & 1) {
                    float2 o; o.x = v0; o.y = v1;
                    *(float2*)(C + off) = o;
                }
                if (OUT & 2) {
                    uint32_t hi, lo;
                    pack_split2(v0, v1, hi, lo);
                    *(uint32_t*)((char*)Ch + off * 2) = hi;
                    *(uint32_t*)((char*)Cl + off * 2) = lo;
                }
            }
        }
    }
}

template<int EPI, int OUT>
__global__ void __launch_bounds__(256, 2) gemm_bf(
    const __nv_bfloat16* __restrict__ Ah, const __nv_bfloat16* __restrict__ Al,
    const __nv_bfloat16* __restrict__ Bh, const __nv_bfloat16* __restrict__ Bl,
    const float* __restrict__ bias, const float* __restrict__ R,
    float* __restrict__ C, __nv_bfloat16* __restrict__ Ch, __nv_bfloat16* __restrict__ Cl,
    int M, int N, int K)
{
    const int bx = blockIdx.x, by = blockIdx.y;
    gemm_body<EPI, OUT>(Ah + (size_t)(by * 128) * K, Al + (size_t)(by * 128) * K,
                        Bh + bx * 128, Bl + bx * 128,
                        bias, R, C, Ch, Cl, N, K, by * 128, bx * 128);
}

__global__ void __launch_bounds__(256, 2) gemm_qkv(
    const __nv_bfloat16* __restrict__ Ah, const __nv_bfloat16* __restrict__ Al,
    const __nv_bfloat16* __restrict__ Wsh, const __nv_bfloat16* __restrict__ Wsl,
    const float* __restrict__ bq, const float* __restrict__ bk, const float* __restrict__ bv,
    __nv_bfloat16* __restrict__ qh, __nv_bfloat16* __restrict__ ql,
    __nv_bfloat16* __restrict__ kh, __nv_bfloat16* __restrict__ kl,
    __nv_bfloat16* __restrict__ vh, __nv_bfloat16* __restrict__ vl)
{
    const int bx = blockIdx.x, by = blockIdx.y;
    const int m = bx >> 2, bxl = bx & 3;
    const size_t woff = (size_t)m * Dn * Dn;
    const float* bias = (m == 0) ? bq : (m == 1) ? bk : bv;
    __nv_bfloat16* Ch = (m == 0) ? qh : (m == 1) ? kh : vh;
    __nv_bfloat16* Cl = (m == 0) ? ql : (m == 1) ? kl : vl;
    gemm_body<0, 2>(Ah + (size_t)(by * 128) * Dn, Al + (size_t)(by * 128) * Dn,
                    Wsh + woff + bxl * 128, Wsl + woff + bxl * 128,
                    bias, nullptr, nullptr, Ch, Cl, Dn, Dn, by * 128, bxl * 128);
}

// ---------------- split kernel ----------------
__global__ void split_kernel(const float* __restrict__ in, __nv_bfloat16* __restrict__ oh,
                             __nv_bfloat16* __restrict__ ol)
{
    int i = (blockIdx.x * 256 + threadIdx.x) * 4;
    float4 a = *(const float4*)(in + i);
    uint32_t h0, l0, h1, l1;
    pack_split2(a.x, a.y, h0, l0);
    pack_split2(a.z, a.w, h1, l1);
    *(uint2*)((char*)oh + (size_t)i * 2) = make_uint2(h0, h1);
    *(uint2*)((char*)ol + (size_t)i * 2) = make_uint2(l0, l1);
}

// ---------------- warp row reduce ----------------
__device__ __forceinline__ float warpSum(float v)
{
#pragma unroll
    for (int o = 16; o > 0; o >>= 1) v += __shfl_xor_sync(0xffffffffu, v, o);
    return v;
}

// ---------------- LayerNorm: 1 warp/row, 512-thread blocks. flags: bit0 remap, bit1 splits ----------------
__global__ void __launch_bounds__(512) ln_kernel(
    const float* __restrict__ in, const float* __restrict__ gg,
    const float* __restrict__ bb, float* __restrict__ out,
    __nv_bfloat16* __restrict__ oh, __nv_bfloat16* __restrict__ ol, int flags)
{
    const int warp = threadIdx.x >> 5, lane = threadIdx.x & 31;
    const int r = blockIdx.x * 16 + warp;
    const float* row = in + (size_t)r * Dn;
    const int orow = (flags & 1) ? ((r / Tn) * Sn + Qn + (r % Tn)) : r;

    float4 v[4]; float s = 0.f;
#pragma unroll
    for (int i = 0; i < 4; i++) {
        v[i] = *(const float4*)(row + (lane + i * 32) * 4);
        s += v[i].x + v[i].y + v[i].z + v[i].w;
    }
    const float mean = warpSum(s) * (1.0f / Dn);
    float vs = 0.f;
#pragma unroll
    for (int i = 0; i < 4; i++) {
        float d0 = v[i].x - mean, d1 = v[i].y - mean;
        float d2 = v[i].z - mean, d3 = v[i].w - mean;
        vs += d0 * d0 + d1 * d1 + d2 * d2 + d3 * d3;
    }
    const float rstd = rsqrtf(warpSum(vs) * (1.0f / Dn) + 1e-12f);
    const size_t ob = (size_t)orow * Dn;
#pragma unroll
    for (int i = 0; i < 4; i++) {
        const int c = (lane + i * 32) * 4;
        float4 g = *(const float4*)(gg + c);
        float4 bbv = *(const float4*)(bb + c);
        float4 o;
        o.x = (v[i].x - mean) * rstd * g.x + bbv.x;
        o.y = (v[i].y - mean) * rstd * g.y + bbv.y;
        o.z = (v[i].z - mean) * rstd * g.z + bbv.z;
        o.w = (v[i].w - mean) * rstd * g.w + bbv.w;
        *(float4*)(out + ob + c) = o;
        if (flags & 2) {
            uint32_t h0, l0, h1, l1;
            pack_split2(o.x, o.y, h0, l0);
            pack_split2(o.z, o.w, h1, l1);
            *(uint2*)((char*)oh + (ob + c) * 2) = make_uint2(h0, h1);
            *(uint2*)((char*)ol + (ob + c) * 2) = make_uint2(l0, l1);
        }
    }
}

// ---------------- embed: concat + pos + mod, LN, splits (1 warp/row, 512-thread blocks) ----------------
__global__ void __launch_bounds__(512) embed_ln_kernel(
    const float* __restrict__ question,
    const float* __restrict__ pos, const float* __restrict__ mod,
    const float* __restrict__ gg, const float* __restrict__ bb,
    float* __restrict__ x,
    __nv_bfloat16* __restrict__ oh, __nv_bfloat16* __restrict__ ol)
{
    const int warp = threadIdx.x >> 5, lane = threadIdx.x & 31;
    const int row = blockIdx.x * 16 + warp;
    const int s = row % Sn, b = row / Sn;
    const float* base = (s < Qn) ? (question + (size_t)(b * Qn + s) * Dn)
                                 : (x + (size_t)row * Dn);
    const float* pe = pos + (size_t)s * Dn;
    const float* me = mod + (s >= Qn ? Dn : 0);

    float4 v[4]; float sum = 0.f;
#pragma unroll
    for (int i = 0; i < 4; i++) {
        const int c = (lane + i * 32) * 4;
        float4 a = *(const float4*)(base + c);
        float4 p = *(const float4*)(pe + c);
        float4 m = *(const float4*)(me + c);
        v[i].x = a.x + p.x + m.x;
        v[i].y = a.y + p.y + m.y;
        v[i].z = a.z + p.z + m.z;
        v[i].w = a.w + p.w + m.w;
        sum += v[i].x + v[i].y + v[i].z + v[i].w;
    }
    const float mean = warpSum(sum) * (1.0f / Dn);
    float vs = 0.f;
#pragma unroll
    for (int i = 0; i < 4; i++) {
        float d0 = v[i].x - mean, d1 = v[i].y - mean;
        float d2 = v[i].z - mean, d3 = v[i].w - mean;
        vs += d0 * d0 + d1 * d1 + d2 * d2 + d3 * d3;
    }
    const float rstd = rsqrtf(warpSum(vs) * (1.0f / Dn) + 1e-12f);
    const size_t ob = (size_t)row * Dn;
#pragma unroll
    for (int i = 0; i < 4; i++) {
        const int c = (lane + i * 32) * 4;
        float4 g = *(const float4*)(gg + c);
        float4 bbv = *(const float4*)(bb + c);
        float4 o;
        o.x = (v[i].x - mean) * rstd * g.x + bbv.x;
        o.y = (v[i].y - mean) * rstd * g.y + bbv.y;
        o.z = (v[i].z - mean) * rstd * g.z + bbv.z;
        o.w = (v[i].w - mean) * rstd * g.w + bbv.w;
        *(float4*)(x + ob + c) = o;
        uint32_t h0, l0, h1, l1;
        pack_split2(o.x, o.y, h0, l0);
        pack_split2(o.z, o.w, h1, l1);
        *(uint2*)((char*)oh + (ob + c) * 2) = make_uint2(h0, h1);
        *(uint2*)((char*)ol + (ob + c) * 2) = make_uint2(l0, l1);
    }
}

// ================ FA2 HMMA attention: async prologue, K+V double-buffered ================
#define AT_QH  0
#define AT_QL  (AT_QH + 18432)
#define AT_K0  (AT_QL + 18432)
#define AT_K1  (AT_K0 + 18432)
#define AT_V0  (AT_K1 + 18432)
#define AT_V1  (AT_V0 + 18432)
#define AT_MB  (AT_V1 + 18432)
#define AT_TOTAL (AT_MB + 2048)         // 112640 -> 2 CTAs/SM

#define SC2 0.18033688f                 // 0.125 * log2(e)

__global__ void __launch_bounds__(256, 2) attn_kernel(
    const __nv_bfloat16* __restrict__ qh, const __nv_bfloat16* __restrict__ ql,
    const __nv_bfloat16* __restrict__ kh, const __nv_bfloat16* __restrict__ kl,
    const __nv_bfloat16* __restrict__ vh, const __nv_bfloat16* __restrict__ vl,
    const int* __restrict__ mask,
    __nv_bfloat16* __restrict__ ctxh, __nv_bfloat16* __restrict__ ctxl)
{
    extern __shared__ char smem[];
    const uint32_t sb = smem_u32(smem);
    float* maskb = (float*)(smem + AT_MB);

    const int tid = threadIdx.x, wid = tid >> 5, lane = tid & 31;
    const int gid = lane >> 2, tig = lane & 3;
    const int qt = blockIdx.x, bh_ = blockIdx.y;
    const int b = bh_ >> 3, h = bh_ & 7;
    const size_t rowbase = (size_t)(b * Sn + qt * 128);

    const int lr0 = tid >> 3, lc8 = (tid & 7) * 8;

    // ---- fully async prologue: K0+V0 first, then Q (all one cp.async group) ----
#pragma unroll
    for (int it = 0; it < 2; it++) {
        int r = lr0 + it * 32;
        size_t go = (size_t)(b * Sn + r) * Dn + h * DHn + lc8;
        uint32_t so = (uint32_t)(r * 72 + lc8) * 2;
        cp16(sb + AT_K0 + so, kh + go);
        cp16(sb + AT_K0 + 9216 + so, kl + go);
        cp16(sb + AT_V0 + so, vh + go);
        cp16(sb + AT_V0 + 9216 + so, vl + go);
    }
#pragma unroll
    for (int it = 0; it < 4; it++) {
        int idx = tid + it * 256;
        int r = idx >> 3, c8 = (idx & 7) * 8;
        size_t go = (rowbase + r) * Dn + h * DHn + c8;
        uint32_t so = (uint32_t)(r * 72 + c8) * 2;
        cp16(sb + AT_QH + so, qh + go);
        cp16(sb + AT_QL + so, ql + go);
    }
    CP_COMMIT();
#pragma unroll
    for (int i = 0; i < 2; i++) {
        int idx = tid + i * 256;
        maskb[idx] = (mask[b * Sn + idx] == 0) ? -1e30f : 0.f;
    }

    float o[8][4];
#pragma unroll
    for (int nb = 0; nb < 8; nb++)
#pragma unroll
        for (int e = 0; e < 4; e++) o[nb][e] = 0.f;
    float m0 = -1e30f, m1 = -1e30f, l0 = 0.f, l1 = 0.f;

    const uint32_t aqb = ((uint32_t)((wid * 16 + (lane & 15)) * 72 + (lane >> 4) * 8)) * 2;
    const uint32_t n_add = (lane & 7) + ((lane >> 4) << 3);
    const uint32_t k_add = ((lane >> 3) & 1) * 8;

    for (int kt = 0; kt < 8; kt++) {
        const uint32_t kb = (kt & 1) ? AT_K1 : AT_K0;
        const uint32_t vb = (kt & 1) ? AT_V1 : AT_V0;
        if (kt) __syncthreads();
        if (kt < 7) {
            const uint32_t kn = (kt & 1) ? AT_K0 : AT_K1;
            const uint32_t vn = (kt & 1) ? AT_V0 : AT_V1;
#pragma unroll
            for (int it = 0; it < 2; it++) {
                int r = lr0 + it * 32;
                size_t go = (size_t)(b * Sn + (kt + 1) * 64 + r) * Dn + h * DHn + lc8;
                uint32_t so = (uint32_t)(r * 72 + lc8) * 2;
                cp16(sb + kn + so, kh + go);
                cp16(sb + kn + 9216 + so, kl + go);
                cp16(sb + vn + so, vh + go);
                cp16(sb + vn + 9216 + so, vl + go);
            }
            CP_COMMIT();
            CP_WAIT1();
        } else {
            CP_WAIT0();
        }
        __syncthreads();

        float s[8][4];
#pragma unroll
        for (int nb = 0; nb < 8; nb++)
#pragma unroll
            for (int e = 0; e < 4; e++) s[nb][e] = 0.f;
#pragma unroll
        for (int ks = 0; ks < 4; ks++) {
            uint32_t qhf[4], qlf[4];
            ldsm_x4(qhf[0], qhf[1], qhf[2], qhf[3], sb + AT_QH + aqb + ks * 32);
            ldsm_x4(qlf[0], qlf[1], qlf[2], qlf[3], sb + AT_QL + aqb + ks * 32);
#pragma unroll
            for (int np = 0; np < 4; np++) {
                uint32_t koff = ((uint32_t)((np * 16 + n_add) * 72 + ks * 16 + k_add)) * 2;
                uint32_t bh4[4], bl4[4];
                ldsm_x4(bh4[0], bh4[1], bh4[2], bh4[3], sb + kb + koff);
                ldsm_x4(bl4[0], bl4[1], bl4[2], bl4[3], sb + kb + 9216 + koff);
                mma16816(s[2 * np],     qhf, bh4);
                mma16816(s[2 * np],     qhf, bl4);
                mma16816(s[2 * np],     qlf, bh4);
                mma16816(s[2 * np + 1], qhf, bh4 + 2);
                mma16816(s[2 * np + 1], qhf, bl4 + 2);
                mma16816(s[2 * np + 1], qlf, bh4 + 2);
            }
        }
#pragma unroll
        for (int nb = 0; nb < 8; nb++) {
            const int col = kt * 64 + nb * 8 + 2 * tig;
            const float mc0 = maskb[col], mc1 = maskb[col + 1];
            s[nb][0] = s[nb][0] * SC2 + mc0;
            s[nb][1] = s[nb][1] * SC2 + mc1;
            s[nb][2] = s[nb][2] * SC2 + mc0;
            s[nb][3] = s[nb][3] * SC2 + mc1;
        }

        float t0 = -1e30f, t1 = -1e30f;
#pragma unroll
        for (int nb = 0; nb < 8; nb++) {
            t0 = fmaxf(t0, fmaxf(s[nb][0], s[nb][1]));
            t1 = fmaxf(t1, fmaxf(s[nb][2], s[nb][3]));
        }
        t0 = fmaxf(t0, __shfl_xor_sync(0xffffffffu, t0, 1));
        t0 = fmaxf(t0, __shfl_xor_sync(0xffffffffu, t0, 2));
        t1 = fmaxf(t1, __shfl_xor_sync(0xffffffffu, t1, 1));
        t1 = fmaxf(t1, __shfl_xor_sync(0xffffffffu, t1, 2));
        const float mn0 = fmaxf(m0, t0), mn1 = fmaxf(m1, t1);
        const float f0 = fexp2(m0 - mn0), f1 = fexp2(m1 - mn1);
        m0 = mn0; m1 = mn1;
        float ls0 = 0.f, ls1 = 0.f;
#pragma unroll
        for (int nb = 0; nb < 8; nb++) {
            s[nb][0] = fexp2(s[nb][0] - mn0);
            s[nb][1] = fexp2(s[nb][1] - mn0);
            s[nb][2] = fexp2(s[nb][2] - mn1);
            s[nb][3] = fexp2(s[nb][3] - mn1);
            ls0 += s[nb][0] + s[nb][1];
            ls1 += s[nb][2] + s[nb][3];
        }
        ls0 += __shfl_xor_sync(0xffffffffu, ls0, 1);
        ls0 += __shfl_xor_sync(0xffffffffu, ls0, 2);
        ls1 += __shfl_xor_sync(0xffffffffu, ls1, 1);
        ls1 += __shfl_xor_sync(0xffffffffu, ls1, 2);
        l0 = l0 * f0 + ls0;
        l1 = l1 * f1 + ls1;
#pragma unroll
        for (int nb = 0; nb < 8; nb++) {
            o[nb][0] *= f0; o[nb][1] *= f0;
            o[nb][2] *= f1; o[nb][3] *= f1;
        }

#pragma unroll
        for (int ks = 0; ks < 4; ks++) {
            uint32_t ph[4], pl[4];
            pack_split2(s[2 * ks][0],     s[2 * ks][1],     ph[0], pl[0]);
            pack_split2(s[2 * ks][2],     s[2 * ks][3],     ph[1], pl[1]);
            pack_split2(s[2 * ks + 1][0], s[2 * ks + 1][1], ph[2], pl[2]);
            pack_split2(s[2 * ks + 1][2], s[2 * ks + 1][3], ph[3], pl[3]);
#pragma unroll
            for (int np = 0; np < 4; np++) {
                uint32_t voff = ((uint32_t)((ks * 16 + (lane & 15)) * 72
                                + np * 16 + ((lane >> 4) & 1) * 8)) * 2;
                uint32_t vb4h[4], vb4l[4];
                ldsm_x4t(vb4h[0], vb4h[1], vb4h[2], vb4h[3], sb + vb + voff);
                ldsm_x4t(vb4l[0], vb4l[1], vb4l[2], vb4l[3], sb + vb + 9216 + voff);
                mma16816(o[2 * np],     ph, vb4h);
                mma16816(o[2 * np],     ph, vb4l);
                mma16816(o[2 * np],     pl, vb4h);
                mma16816(o[2 * np + 1], ph, vb4h + 2);
                mma16816(o[2 * np + 1], ph, vb4l + 2);
                mma16816(o[2 * np + 1], pl, vb4h + 2);
            }
        }
    }

    {
        const int r0 = wid * 16 + gid;
        const float inv0 = 1.0f / l0, inv1 = 1.0f / l1;
#pragma unroll
        for (int nb = 0; nb < 8; nb++) {
            const int col = h * DHn + nb * 8 + 2 * tig;
            uint32_t hA, lA, hB, lB;
            pack_split2(o[nb][0] * inv0, o[nb][1] * inv0, hA, lA);
            pack_split2(o[nb][2] * inv1, o[nb][3] * inv1, hB, lB);
            size_t off0 = (rowbase + r0) * Dn + col;
            size_t off1 = (rowbase + r0 + 8) * Dn + col;
            *(uint32_t*)((char*)ctxh + off0 * 2) = hA;
            *(uint32_t*)((char*)ctxl + off0 * 2) = lA;
            *(uint32_t*)((char*)ctxh + off1 * 2) = hB;
            *(uint32_t*)((char*)ctxl + off1 * 2) = lB;
        }
    }
}

// ---------------- host orchestration ----------------
extern "C" void kernel_launch(void* const* d_in, const int* in_sizes, int n_in,
                              void* d_out, int out_size)
{
    const float* video    = (const float*)d_in[0];
    const float* question = (const float*)d_in[1];
    const int*   mask     = (const int*)  d_in[2];
    const float* pos_emb  = (const float*)d_in[3];
    const float* mod_emb  = (const float*)d_in[4];
    const float* Wv       = (const float*)d_in[5];
    const float* bv       = (const float*)d_in[6];
    const float* nv_g     = (const float*)d_in[7];
    const float* nv_b     = (const float*)d_in[8];
    const float* emb_g    = (const float*)d_in[9];
    const float* emb_b    = (const float*)d_in[10];
    const float* Wq       = (const float*)d_in[11];
    const float* bq       = (const float*)d_in[12];
    const float* Wk       = (const float*)d_in[13];
    const float* bk       = (const float*)d_in[14];
    const float* Wva      = (const float*)d_in[15];
    const float* bva      = (const float*)d_in[16];
    const float* Wo       = (const float*)d_in[17];
    const float* bo       = (const float*)d_in[18];
    const float* ln1_g    = (const float*)d_in[19];
    const float* ln1_b    = (const float*)d_in[20];
    const float* W1       = (const float*)d_in[21];
    const float* b1       = (const float*)d_in[22];
    const float* W2       = (const float*)d_in[23];
    const float* b2       = (const float*)d_in[24];
    const float* ln2_g    = (const float*)d_in[25];
    const float* ln2_b    = (const float*)d_in[26];

    float *x, *t1;
    __nv_bfloat16 *xh, *xl, *aqh, *aql, *akh, *akl, *avh, *avl;
    __nv_bfloat16 *ch, *cl, *hh, *hl, *vh, *vl;
    __nv_bfloat16 *wvh, *wvl, *wqkvh, *wqkvl, *woh, *wol, *w1h, *w1l, *w2h, *w2l;
    cudaGetSymbolAddress((void**)&x,   g_x);
    cudaGetSymbolAddress((void**)&t1,  g_t1);
    cudaGetSymbolAddress((void**)&xh,  g_xh);  cudaGetSymbolAddress((void**)&xl,  g_xl);
    cudaGetSymbolAddress((void**)&aqh, g_aqh); cudaGetSymbolAddress((void**)&aql, g_aql);
    cudaGetSymbolAddress((void**)&akh, g_akh); cudaGetSymbolAddress((void**)&akl, g_akl);
    cudaGetSymbolAddress((void**)&avh, g_avh); cudaGetSymbolAddress((void**)&avl, g_avl);
    cudaGetSymbolAddress((void**)&ch,  g_ch);  cudaGetSymbolAddress((void**)&cl,  g_cl);
    cudaGetSymbolAddress((void**)&hh,  g_hh);  cudaGetSymbolAddress((void**)&hl,  g_hl);
    cudaGetSymbolAddress((void**)&vh,  g_vh);  cudaGetSymbolAddress((void**)&vl,  g_vl);
    cudaGetSymbolAddress((void**)&wvh,   g_wvh);   cudaGetSymbolAddress((void**)&wvl,   g_wvl);
    cudaGetSymbolAddress((void**)&wqkvh, g_wqkvh); cudaGetSymbolAddress((void**)&wqkvl, g_wqkvl);
    cudaGetSymbolAddress((void**)&woh,   g_woh);   cudaGetSymbolAddress((void**)&wol,   g_wol);
    cudaGetSymbolAddress((void**)&w1h,   g_w1h);   cudaGetSymbolAddress((void**)&w1l,   g_w1l);
    cudaGetSymbolAddress((void**)&w2h,   g_w2h);   cudaGetSymbolAddress((void**)&w2l,   g_w2l);

    static cudaStream_t s1 = nullptr;
    static cudaEvent_t evFork = nullptr, evWv = nullptr, evW = nullptr;
    static bool attr_set = false;
    if (!attr_set) {
        cudaFuncSetAttribute(attn_kernel, cudaFuncAttributeMaxDynamicSharedMemorySize, AT_TOTAL);
        cudaFuncSetAttribute(gemm_bf<0,1>, cudaFuncAttributeMaxDynamicSharedMemorySize, SM_TOTAL);
        cudaFuncSetAttribute(gemm_bf<1,2>, cudaFuncAttributeMaxDynamicSharedMemorySize, SM_TOTAL);
        cudaFuncSetAttribute(gemm_bf<2,1>, cudaFuncAttributeMaxDynamicSharedMemorySize, SM_TOTAL);
        cudaFuncSetAttribute(gemm_qkv, cudaFuncAttributeMaxDynamicSharedMemorySize, SM_TOTAL);
        cudaStreamCreateWithFlags(&s1, cudaStreamNonBlocking);
        cudaEventCreateWithFlags(&evFork, cudaEventDisableTiming);
        cudaEventCreateWithFlags(&evWv, cudaEventDisableTiming);
        cudaEventCreateWithFlags(&evW, cudaEventDisableTiming);
        attr_set = true;
    }

    // ---- fork side stream: weight splits concurrent with video path ----
    cudaEventRecord(evFork, 0);
    cudaStreamWaitEvent(s1, evFork, 0);
    split_kernel<<<(FDn * Dn) / 1024, 256, 0, s1>>>(Wv, wvh, wvl);
    cudaEventRecord(evWv, s1);
    for (int i = 0; i < NLn; i++) {
        const size_t wD = (size_t)i * Dn * Dn;
        const size_t qD = (size_t)i * 3 * Dn * Dn;
        split_kernel<<<(Dn * Dn) / 1024, 256, 0, s1>>>(Wq  + wD, wqkvh + qD,               wqkvl + qD);
        split_kernel<<<(Dn * Dn) / 1024, 256, 0, s1>>>(Wk  + wD, wqkvh + qD + Dn * Dn,     wqkvl + qD + Dn * Dn);
        split_kernel<<<(Dn * Dn) / 1024, 256, 0, s1>>>(Wva + wD, wqkvh + qD + 2 * Dn * Dn, wqkvl + qD + 2 * Dn * Dn);
        split_kernel<<<(Dn * Dn) / 1024, 256, 0, s1>>>(Wo + wD, woh + wD, wol + wD);
        split_kernel<<<(Dn * FFn) / 1024, 256, 0, s1>>>(W1 + (size_t)i * Dn * FFn,
                                                        w1h + (size_t)i * Dn * FFn,
                                                        w1l + (size_t)i * Dn * FFn);
        split_kernel<<<(FFn * Dn) / 1024, 256, 0, s1>>>(W2 + (size_t)i * FFn * Dn,
                                                        w2h + (size_t)i * FFn * Dn,
                                                        w2l + (size_t)i * FFn * Dn);
    }
    cudaEventRecord(evW, s1);

    // ---- main stream: video path ----
    split_kernel<<<(BTr * FDn) / 1024, 256>>>(video, vh, vl);
    cudaStreamWaitEvent(0, evWv, 0);
    gemm_bf<0,1><<<dim3(Dn / 128, BTr / 128), 256, SM_TOTAL>>>(
        vh, vl, wvh, wvl, bv, nullptr, t1, nullptr, nullptr, BTr, Dn, FDn);
    ln_kernel<<<BTr / 16, 512>>>(t1, nv_g, nv_b, x, xh, xl, 1);
    embed_ln_kernel<<<BSr / 16, 512>>>(question, pos_emb, mod_emb, emb_g, emb_b, x, xh, xl);
    cudaStreamWaitEvent(0, evW, 0);

    for (int i = 0; i < NLn; i++) {
        const size_t wD = (size_t)i * Dn * Dn;
        const size_t qD = (size_t)i * 3 * Dn * Dn;
        gemm_qkv<<<dim3(12, BSr / 128), 256, SM_TOTAL>>>(
            xh, xl, wqkvh + qD, wqkvl + qD, bq + i * Dn, bk + i * Dn, bva + i * Dn,
            aqh, aql, akh, akl, avh, avl);

        attn_kernel<<<dim3(Sn / 128, Bn * Hn), 256, AT_TOTAL>>>(
            aqh, aql, akh, akl, avh, avl, mask, ch, cl);

        gemm_bf<2,1><<<dim3(Dn / 128, BSr / 128), 256, SM_TOTAL>>>(
            ch, cl, woh + wD, wol + wD, bo + i * Dn, x, t1, nullptr, nullptr, BSr, Dn, Dn);
        ln_kernel<<<BSr / 16, 512>>>(t1, ln1_g + i * Dn, ln1_b + i * Dn, x, xh, xl, 2);

        gemm_bf<1,2><<<dim3(FFn / 128, BSr / 128), 256, SM_TOTAL>>>(
            xh, xl, w1h + (size_t)i * Dn * FFn, w1l + (size_t)i * Dn * FFn,
            b1 + i * FFn, nullptr, nullptr, hh, hl, BSr, FFn, Dn);
        gemm_bf<2,1><<<dim3(Dn / 128, BSr / 128), 256, SM_TOTAL>>>(
            hh, hl, w2h + (size_t)i * FFn * Dn, w2l + (size_t)i * FFn * Dn,
            b2 + i * Dn, x, t1, nullptr, nullptr, BSr, Dn, FFn);

        if (i == NLn - 1) {
            ln_kernel<<<BSr / 16, 512>>>(t1, ln2_g + i * Dn, ln2_b + i * Dn,
                                         (float*)d_out, xh, xl, 0);
        } else {
            ln_kernel<<<BSr / 16, 512>>>(t1, ln2_g + i * Dn, ln2_b + i * Dn, x, xh, xl, 2);
        }
    }
}

// round 16
// speedup vs baseline: 1.0073x; 1.0073x over previous
#include <cuda_runtime.h>
#include <cuda_bf16.h>
#include <math.h>
#include <stdint.h>

// ---------------- problem constants ----------------
#define Bn   64
#define Qn   64
#define Tn   448
#define Dn   512
#define FDn  1024
#define Hn   8
#define NLn  2
#define FFn  2048
#define Sn   512
#define DHn  64
#define BSr  (Bn*Sn)
#define BTr  (Bn*Tn)

// ---------------- scratch ----------------
__device__ float g_x [BSr*Dn];
__device__ float g_t1[BSr*Dn];
__device__ __nv_bfloat16 g_xh [BSr*Dn],  g_xl [BSr*Dn];
__device__ __nv_bfloat16 g_aqh[BSr*Dn],  g_aql[BSr*Dn];
__device__ __nv_bfloat16 g_akh[BSr*Dn],  g_akl[BSr*Dn];
__device__ __nv_bfloat16 g_avh[BSr*Dn],  g_avl[BSr*Dn];
__device__ __nv_bfloat16 g_ch [BSr*Dn],  g_cl [BSr*Dn];
__device__ __nv_bfloat16 g_hh [BSr*FFn], g_hl [BSr*FFn];
__device__ __nv_bfloat16 g_vh [BTr*FDn], g_vl [BTr*FDn];
__device__ __nv_bfloat16 g_wvh [FDn*Dn],        g_wvl [FDn*Dn];
__device__ __nv_bfloat16 g_wqkvh[NLn*3*Dn*Dn],  g_wqkvl[NLn*3*Dn*Dn];
__device__ __nv_bfloat16 g_woh [NLn*Dn*Dn],     g_wol [NLn*Dn*Dn];
__device__ __nv_bfloat16 g_w1h [NLn*Dn*FFn],    g_w1l [NLn*Dn*FFn];
__device__ __nv_bfloat16 g_w2h [NLn*FFn*Dn],    g_w2l [NLn*FFn*Dn];

// ---------------- helpers ----------------
__device__ __forceinline__ uint32_t smem_u32(const void* p) {
    uint32_t a;
    asm("{ .reg .u64 t; cvta.to.shared.u64 t, %1; cvt.u32.u64 %0, t; }" : "=r"(a) : "l"(p));
    return a;
}
__device__ __forceinline__ void split_bf16(float x, __nv_bfloat16& h, __nv_bfloat16& l) {
    h = __float2bfloat16_rn(x);
    l = __float2bfloat16_rn(x - __bfloat162float(h));
}
__device__ __forceinline__ uint32_t pack2(__nv_bfloat16 a, __nv_bfloat16 b) {
    __nv_bfloat162 v(a, b);
    return *reinterpret_cast<uint32_t*>(&v);
}
__device__ __forceinline__ void pack_split2(float a, float b, uint32_t& hi, uint32_t& lo) {
    __nv_bfloat16 ha, la, hb, lb;
    split_bf16(a, ha, la);
    split_bf16(b, hb, lb);
    hi = pack2(ha, hb);
    lo = pack2(la, lb);
}
__device__ __forceinline__ void ldsm_x4(uint32_t& r0, uint32_t& r1, uint32_t& r2, uint32_t& r3,
                                        uint32_t addr) {
    asm volatile("ldmatrix.sync.aligned.m8n8.x4.shared.b16 {%0,%1,%2,%3}, [%4];"
                 : "=r"(r0), "=r"(r1), "=r"(r2), "=r"(r3) : "r"(addr));
}
__device__ __forceinline__ void ldsm_x4t(uint32_t& r0, uint32_t& r1, uint32_t& r2, uint32_t& r3,
                                         uint32_t addr) {
    asm volatile("ldmatrix.sync.aligned.m8n8.x4.trans.shared.b16 {%0,%1,%2,%3}, [%4];"
                 : "=r"(r0), "=r"(r1), "=r"(r2), "=r"(r3) : "r"(addr));
}
__device__ __forceinline__ void mma16816(float* d, const uint32_t* a, const uint32_t* b) {
    asm volatile(
        "mma.sync.aligned.m16n8k16.row.col.f32.bf16.bf16.f32 "
        "{%0,%1,%2,%3}, {%4,%5,%6,%7}, {%8,%9}, {%0,%1,%2,%3};"
        : "+f"(d[0]), "+f"(d[1]), "+f"(d[2]), "+f"(d[3])
        : "r"(a[0]), "r"(a[1]), "r"(a[2]), "r"(a[3]), "r"(b[0]), "r"(b[1]));
}
__device__ __forceinline__ void cp16(uint32_t s, const void* g) {
    asm volatile("cp.async.cg.shared.global [%0], [%1], 16;" :: "r"(s), "l"(g));
}
#define CP_COMMIT() asm volatile("cp.async.commit_group;" ::: "memory")
#define CP_WAIT0()  asm volatile("cp.async.wait_group 0;" ::: "memory")
#define CP_WAIT1()  asm volatile("cp.async.wait_group 1;" ::: "memory")

__device__ __forceinline__ float fexp2(float y) {
    y = fmaxf(y, -126.f);
    float n = rintf(y);
    float r = y - n;
    float p = fmaf(1.333356e-3f, r, 9.618129e-3f);
    p = fmaf(p, r, 5.5504109e-2f);
    p = fmaf(p, r, 2.40226507e-1f);
    p = fmaf(p, r, 6.93147181e-1f);
    p = fmaf(p, r, 1.0f);
    return p * __int_as_float(((int)n + 127) << 23);
}

// ---------------- GEMM smem layout: 128x128 tile, BK=32, 3-stage ----------------
#define ASTRIDE 40
#define BSTRIDE 136
#define STG_A   (128 * ASTRIDE * 2)
#define STG_B   (32 * BSTRIDE * 2)
#define STAGE_BYTES (2 * STG_A + 2 * STG_B)
#define NSTAGE  3
#define SM_TOTAL (NSTAGE * STAGE_BYTES)      // 113664 -> 2 CTAs/SM

__device__ __forceinline__ void gemm_compute(uint32_t sbase, uint32_t a_off, int warp_n, int lane,
                                             float (&acc)[2][8][4])
{
#pragma unroll
    for (int ks = 0; ks < 2; ks++) {
        uint32_t ah[2][4], al[2][4];
#pragma unroll
        for (int mt = 0; mt < 2; mt++) {
            uint32_t aa = sbase + a_off + (uint32_t)(mt * 16 * ASTRIDE) * 2 + ks * 32;
            ldsm_x4(ah[mt][0], ah[mt][1], ah[mt][2], ah[mt][3], aa);
            ldsm_x4(al[mt][0], al[mt][1], al[mt][2], al[mt][3], aa + STG_A);
        }
#pragma unroll
        for (int ntp = 0; ntp < 4; ntp++) {
            uint32_t boff = sbase + 2 * STG_A +
                (uint32_t)((ks * 16 + (lane & 15)) * BSTRIDE
                           + warp_n * 64 + ntp * 16 + ((lane >> 4) & 1) * 8) * 2;
            uint32_t bh[4], bl[4];
            ldsm_x4t(bh[0], bh[1], bh[2], bh[3], boff);
            ldsm_x4t(bl[0], bl[1], bl[2], bl[3], boff + STG_B);
#pragma unroll
            for (int mt = 0; mt < 2; mt++) {
                mma16816(acc[mt][2 * ntp],     ah[mt], bh);
                mma16816(acc[mt][2 * ntp],     ah[mt], bl);
                mma16816(acc[mt][2 * ntp],     al[mt], bh);
                mma16816(acc[mt][2 * ntp + 1], ah[mt], bh + 2);
                mma16816(acc[mt][2 * ntp + 1], ah[mt], bl + 2);
                mma16816(acc[mt][2 * ntp + 1], al[mt], bh + 2);
            }
        }
    }
}

// ---- shared GEMM body: CTA tile 128x128 at (row0, col0); A/B pre-offset ----
template<int EPI, int OUT>
__device__ __forceinline__ void gemm_body(
    const __nv_bfloat16* __restrict__ Agh, const __nv_bfloat16* __restrict__ Agl,
    const __nv_bfloat16* __restrict__ Bgh, const __nv_bfloat16* __restrict__ Bgl,
    const float* __restrict__ bias, const float* __restrict__ R,
    float* __restrict__ C, __nv_bfloat16* __restrict__ Ch, __nv_bfloat16* __restrict__ Cl,
    int N, int K, int row0g, int col0g)
{
    extern __shared__ char smem[];
    const uint32_t sb = smem_u32(smem);
    const int tid = threadIdx.x, wid = tid >> 5, lane = tid & 31;
    const int warp_m = wid & 3, warp_n = wid >> 2;
    const int gid = lane >> 2, tig = lane & 3;
    const int a_row = tid >> 2, a_seg = tid & 3;
    const int b_row = tid >> 4, b_seg = tid & 15;

    float acc[2][8][4];
#pragma unroll
    for (int mt = 0; mt < 2; mt++)
#pragma unroll
        for (int nt = 0; nt < 8; nt++)
#pragma unroll
            for (int e = 0; e < 4; e++) acc[mt][nt][e] = 0.f;

    const uint32_t a_off = (uint32_t)((warp_m * 32 + (lane & 15)) * ASTRIDE + (lane >> 4) * 8) * 2;
    const int nch = K >> 5;

#define LOAD_STAGE(slot, kc) do { \
    const uint32_t sbase_ = sb + (slot) * STAGE_BYTES; \
    _Pragma("unroll") \
    for (int i = 0; i < 2; i++) { \
        int row = a_row + i * 64; \
        uint32_t so = sbase_ + (uint32_t)(row * ASTRIDE + a_seg * 8) * 2; \
        size_t go = (size_t)row * K + (kc) * 32 + a_seg * 8; \
        cp16(so, Agh + go); \
        cp16(so + STG_A, Agl + go); \
    } \
    _Pragma("unroll") \
    for (int i = 0; i < 2; i++) { \
        int kk = b_row + i * 16; \
        uint32_t so = sbase_ + 2 * STG_A + (uint32_t)(kk * BSTRIDE + b_seg * 8) * 2; \
        size_t go = (size_t)((kc) * 32 + kk) * N + b_seg * 8; \
        cp16(so, Bgh + go); \
        cp16(so + STG_B, Bgl + go); \
    } \
} while (0)

    LOAD_STAGE(0, 0); CP_COMMIT();
    LOAD_STAGE(1, 1); CP_COMMIT();

    for (int kc = 0; kc < nch; kc++) {
        CP_WAIT1();
        __syncthreads();
        const int nk = kc + 2;
        if (nk < nch) { LOAD_STAGE(nk % NSTAGE, nk); }
        CP_COMMIT();
        gemm_compute(sb + (kc % NSTAGE) * STAGE_BYTES, a_off, warp_n, lane, acc);
    }
#undef LOAD_STAGE

#pragma unroll
    for (int mt = 0; mt < 2; mt++) {
        const int row0 = row0g + warp_m * 32 + mt * 16 + gid;
#pragma unroll
        for (int nt = 0; nt < 8; nt++) {
            const int col = col0g + warp_n * 64 + nt * 8 + 2 * tig;
            float2 bs = *(const float2*)(bias + col);
#pragma unroll
            for (int half = 0; half < 2; half++) {
                const int row = row0 + half * 8;
                const size_t off = (size_t)row * N + col;
                float v0 = acc[mt][nt][half * 2 + 0] + bs.x;
                float v1 = acc[mt][nt][half * 2 + 1] + bs.y;
                if (EPI == 1) {
                    v0 = 0.5f * v0 * (1.f + erff(v0 * 0.70710678118654752f));
                    v1 = 0.5f * v1 * (1.f + erff(v1 * 0.70710678118654752f));
                } else if (EPI == 2) {
                    float2 rr = *(const float2*)(R + off);
                    v0 += rr.x; v1 += rr.y;
                }
                if (OUT & 1) {
                    float2 o; o.x = v0; o.y = v1;
                    *(float2*)(C + off) = o;
                }
                if (OUT & 2) {
                    uint32_t hi, lo;
                    pack_split2(v0, v1, hi, lo);
                    *(uint32_t*)((char*)Ch + off * 2) = hi;
                    *(uint32_t*)((char*)Cl + off * 2) = lo;
                }
            }
        }
    }
}

template<int EPI, int OUT>
__global__ void __launch_bounds__(256, 2) gemm_bf(
    const __nv_bfloat16* __restrict__ Ah, const __nv_bfloat16* __restrict__ Al,
    const __nv_bfloat16* __restrict__ Bh, const __nv_bfloat16* __restrict__ Bl,
    const float* __restrict__ bias, const float* __restrict__ R,
    float* __restrict__ C, __nv_bfloat16* __restrict__ Ch, __nv_bfloat16* __restrict__ Cl,
    int M, int N, int K)
{
    const int bx = blockIdx.x, by = blockIdx.y;
    gemm_body<EPI, OUT>(Ah + (size_t)(by * 128) * K, Al + (size_t)(by * 128) * K,
                        Bh + bx * 128, Bl + bx * 128,
                        bias, R, C, Ch, Cl, N, K, by * 128, bx * 128);
}

__global__ void __launch_bounds__(256, 2) gemm_qkv(
    const __nv_bfloat16* __restrict__ Ah, const __nv_bfloat16* __restrict__ Al,
    const __nv_bfloat16* __restrict__ Wsh, const __nv_bfloat16* __restrict__ Wsl,
    const float* __restrict__ bq, const float* __restrict__ bk, const float* __restrict__ bv,
    __nv_bfloat16* __restrict__ qh, __nv_bfloat16* __restrict__ ql,
    __nv_bfloat16* __restrict__ kh, __nv_bfloat16* __restrict__ kl,
    __nv_bfloat16* __restrict__ vh, __nv_bfloat16* __restrict__ vl)
{
    const int bx = blockIdx.x, by = blockIdx.y;
    const int m = bx >> 2, bxl = bx & 3;
    const size_t woff = (size_t)m * Dn * Dn;
    const float* bias = (m == 0) ? bq : (m == 1) ? bk : bv;
    __nv_bfloat16* Ch = (m == 0) ? qh : (m == 1) ? kh : vh;
    __nv_bfloat16* Cl = (m == 0) ? ql : (m == 1) ? kl : vl;
    gemm_body<0, 2>(Ah + (size_t)(by * 128) * Dn, Al + (size_t)(by * 128) * Dn,
                    Wsh + woff + bxl * 128, Wsl + woff + bxl * 128,
                    bias, nullptr, nullptr, Ch, Cl, Dn, Dn, by * 128, bxl * 128);
}

// ---------------- split kernel ----------------
__global__ void split_kernel(const float* __restrict__ in, __nv_bfloat16* __restrict__ oh,
                             __nv_bfloat16* __restrict__ ol)
{
    int i = (blockIdx.x * 256 + threadIdx.x) * 4;
    float4 a = *(const float4*)(in + i);
    uint32_t h0, l0, h1, l1;
    pack_split2(a.x, a.y, h0, l0);
    pack_split2(a.z, a.w, h1, l1);
    *(uint2*)((char*)oh + (size_t)i * 2) = make_uint2(h0, h1);
    *(uint2*)((char*)ol + (size_t)i * 2) = make_uint2(l0, l1);
}

// ---------------- warp row reduce ----------------
__device__ __forceinline__ float warpSum(float v)
{
#pragma unroll
    for (int o = 16; o > 0; o >>= 1) v += __shfl_xor_sync(0xffffffffu, v, o);
    return v;
}

// ---------------- LayerNorm: 1 warp/row. flags: bit0 remap, bit1 splits ----------------
__global__ void __launch_bounds__(256) ln_kernel(
    const float* __restrict__ in, const float* __restrict__ gg,
    const float* __restrict__ bb, float* __restrict__ out,
    __nv_bfloat16* __restrict__ oh, __nv_bfloat16* __restrict__ ol, int flags)
{
    const int warp = threadIdx.x >> 5, lane = threadIdx.x & 31;
    const int r = blockIdx.x * 8 + warp;
    const float* row = in + (size_t)r * Dn;
    const int orow = (flags & 1) ? ((r / Tn) * Sn + Qn + (r % Tn)) : r;

    float4 v[4]; float s = 0.f;
#pragma unroll
    for (int i = 0; i < 4; i++) {
        v[i] = *(const float4*)(row + (lane + i * 32) * 4);
        s += v[i].x + v[i].y + v[i].z + v[i].w;
    }
    const float mean = warpSum(s) * (1.0f / Dn);
    float vs = 0.f;
#pragma unroll
    for (int i = 0; i < 4; i++) {
        float d0 = v[i].x - mean, d1 = v[i].y - mean;
        float d2 = v[i].z - mean, d3 = v[i].w - mean;
        vs += d0 * d0 + d1 * d1 + d2 * d2 + d3 * d3;
    }
    const float rstd = rsqrtf(warpSum(vs) * (1.0f / Dn) + 1e-12f);
    const size_t ob = (size_t)orow * Dn;
#pragma unroll
    for (int i = 0; i < 4; i++) {
        const int c = (lane + i * 32) * 4;
        float4 g = *(const float4*)(gg + c);
        float4 bbv = *(const float4*)(bb + c);
        float4 o;
        o.x = (v[i].x - mean) * rstd * g.x + bbv.x;
        o.y = (v[i].y - mean) * rstd * g.y + bbv.y;
        o.z = (v[i].z - mean) * rstd * g.z + bbv.z;
        o.w = (v[i].w - mean) * rstd * g.w + bbv.w;
        *(float4*)(out + ob + c) = o;
        if (flags & 2) {
            uint32_t h0, l0, h1, l1;
            pack_split2(o.x, o.y, h0, l0);
            pack_split2(o.z, o.w, h1, l1);
            *(uint2*)((char*)oh + (ob + c) * 2) = make_uint2(h0, h1);
            *(uint2*)((char*)ol + (ob + c) * 2) = make_uint2(l0, l1);
        }
    }
}

// ---------------- embed: concat + pos + mod, LN, splits (1 warp/row) ----------------
__global__ void __launch_bounds__(256) embed_ln_kernel(
    const float* __restrict__ question,
    const float* __restrict__ pos, const float* __restrict__ mod,
    const float* __restrict__ gg, const float* __restrict__ bb,
    float* __restrict__ x,
    __nv_bfloat16* __restrict__ oh, __nv_bfloat16* __restrict__ ol)
{
    const int warp = threadIdx.x >> 5, lane = threadIdx.x & 31;
    const int row = blockIdx.x * 8 + warp;
    const int s = row % Sn, b = row / Sn;
    const float* base = (s < Qn) ? (question + (size_t)(b * Qn + s) * Dn)
                                 : (x + (size_t)row * Dn);
    const float* pe = pos + (size_t)s * Dn;
    const float* me = mod + (s >= Qn ? Dn : 0);

    float4 v[4]; float sum = 0.f;
#pragma unroll
    for (int i = 0; i < 4; i++) {
        const int c = (lane + i * 32) * 4;
        float4 a = *(const float4*)(base + c);
        float4 p = *(const float4*)(pe + c);
        float4 m = *(const float4*)(me + c);
        v[i].x = a.x + p.x + m.x;
        v[i].y = a.y + p.y + m.y;
        v[i].z = a.z + p.z + m.z;
        v[i].w = a.w + p.w + m.w;
        sum += v[i].x + v[i].y + v[i].z + v[i].w;
    }
    const float mean = warpSum(sum) * (1.0f / Dn);
    float vs = 0.f;
#pragma unroll
    for (int i = 0; i < 4; i++) {
        float d0 = v[i].x - mean, d1 = v[i].y - mean;
        float d2 = v[i].z - mean, d3 = v[i].w - mean;
        vs += d0 * d0 + d1 * d1 + d2 * d2 + d3 * d3;
    }
    const float rstd = rsqrtf(warpSum(vs) * (1.0f / Dn) + 1e-12f);
    const size_t ob = (size_t)row * Dn;
#pragma unroll
    for (int i = 0; i < 4; i++) {
        const int c = (lane + i * 32) * 4;
        float4 g = *(const float4*)(gg + c);
        float4 bbv = *(const float4*)(bb + c);
        float4 o;
        o.x = (v[i].x - mean) * rstd * g.x + bbv.x;
        o.y = (v[i].y - mean) * rstd * g.y + bbv.y;
        o.z = (v[i].z - mean) * rstd * g.z + bbv.z;
        o.w = (v[i].w - mean) * rstd * g.w + bbv.w;
        *(float4*)(x + ob + c) = o;
        uint32_t h0, l0, h1, l1;
        pack_split2(o.x, o.y, h0, l0);
        pack_split2(o.z, o.w, h1, l1);
        *(uint2*)((char*)oh + (ob + c) * 2) = make_uint2(h0, h1);
        *(uint2*)((char*)ol + (ob + c) * 2) = make_uint2(l0, l1);
    }
}

// ================ FA2 HMMA attention: async prologue, K+V double-buffered ================
#define AT_QH  0
#define AT_QL  (AT_QH + 18432)
#define AT_K0  (AT_QL + 18432)
#define AT_K1  (AT_K0 + 18432)
#define AT_V0  (AT_K1 + 18432)
#define AT_V1  (AT_V0 + 18432)
#define AT_MB  (AT_V1 + 18432)
#define AT_TOTAL (AT_MB + 2048)         // 112640 -> 2 CTAs/SM

#define SC2 0.18033688f                 // 0.125 * log2(e)

__global__ void __launch_bounds__(256, 2) attn_kernel(
    const __nv_bfloat16* __restrict__ qh, const __nv_bfloat16* __restrict__ ql,
    const __nv_bfloat16* __restrict__ kh, const __nv_bfloat16* __restrict__ kl,
    const __nv_bfloat16* __restrict__ vh, const __nv_bfloat16* __restrict__ vl,
    const int* __restrict__ mask,
    __nv_bfloat16* __restrict__ ctxh, __nv_bfloat16* __restrict__ ctxl)
{
    extern __shared__ char smem[];
    const uint32_t sb = smem_u32(smem);
    float* maskb = (float*)(smem + AT_MB);

    const int tid = threadIdx.x, wid = tid >> 5, lane = tid & 31;
    const int gid = lane >> 2, tig = lane & 3;
    const int qt = blockIdx.x, bh_ = blockIdx.y;
    const int b = bh_ >> 3, h = bh_ & 7;
    const size_t rowbase = (size_t)(b * Sn + qt * 128);

    const int lr0 = tid >> 3, lc8 = (tid & 7) * 8;

    // ---- fully async prologue: K0+V0 first, then Q (all one cp.async group) ----
#pragma unroll
    for (int it = 0; it < 2; it++) {
        int r = lr0 + it * 32;
        size_t go = (size_t)(b * Sn + r) * Dn + h * DHn + lc8;
        uint32_t so = (uint32_t)(r * 72 + lc8) * 2;
        cp16(sb + AT_K0 + so, kh + go);
        cp16(sb + AT_K0 + 9216 + so, kl + go);
        cp16(sb + AT_V0 + so, vh + go);
        cp16(sb + AT_V0 + 9216 + so, vl + go);
    }
#pragma unroll
    for (int it = 0; it < 4; it++) {
        int idx = tid + it * 256;
        int r = idx >> 3, c8 = (idx & 7) * 8;
        size_t go = (rowbase + r) * Dn + h * DHn + c8;
        uint32_t so = (uint32_t)(r * 72 + c8) * 2;
        cp16(sb + AT_QH + so, qh + go);
        cp16(sb + AT_QL + so, ql + go);
    }
    CP_COMMIT();
#pragma unroll
    for (int i = 0; i < 2; i++) {
        int idx = tid + i * 256;
        maskb[idx] = (mask[b * Sn + idx] == 0) ? -1e30f : 0.f;
    }

    float o[8][4];
#pragma unroll
    for (int nb = 0; nb < 8; nb++)
#pragma unroll
        for (int e = 0; e < 4; e++) o[nb][e] = 0.f;
    float m0 = -1e30f, m1 = -1e30f, l0 = 0.f, l1 = 0.f;

    const uint32_t aqb = ((uint32_t)((wid * 16 + (lane & 15)) * 72 + (lane >> 4) * 8)) * 2;
    const uint32_t n_add = (lane & 7) + ((lane >> 4) << 3);
    const uint32_t k_add = ((lane >> 3) & 1) * 8;

    for (int kt = 0; kt < 8; kt++) {
        const uint32_t kb = (kt & 1) ? AT_K1 : AT_K0;
        const uint32_t vb = (kt & 1) ? AT_V1 : AT_V0;
        if (kt) __syncthreads();
        if (kt < 7) {
            const uint32_t kn = (kt & 1) ? AT_K0 : AT_K1;
            const uint32_t vn = (kt & 1) ? AT_V0 : AT_V1;
#pragma unroll
            for (int it = 0; it < 2; it++) {
                int r = lr0 + it * 32;
                size_t go = (size_t)(b * Sn + (kt + 1) * 64 + r) * Dn + h * DHn + lc8;
                uint32_t so = (uint32_t)(r * 72 + lc8) * 2;
                cp16(sb + kn + so, kh + go);
                cp16(sb + kn + 9216 + so, kl + go);
                cp16(sb + vn + so, vh + go);
                cp16(sb + vn + 9216 + so, vl + go);
            }
            CP_COMMIT();
            CP_WAIT1();
        } else {
            CP_WAIT0();
        }
        __syncthreads();

        float s[8][4];
#pragma unroll
        for (int nb = 0; nb < 8; nb++)
#pragma unroll
            for (int e = 0; e < 4; e++) s[nb][e] = 0.f;
#pragma unroll
        for (int ks = 0; ks < 4; ks++) {
            uint32_t qhf[4], qlf[4];
            ldsm_x4(qhf[0], qhf[1], qhf[2], qhf[3], sb + AT_QH + aqb + ks * 32);
            ldsm_x4(qlf[0], qlf[1], qlf[2], qlf[3], sb + AT_QL + aqb + ks * 32);
#pragma unroll
            for (int np = 0; np < 4; np++) {
                uint32_t koff = ((uint32_t)((np * 16 + n_add) * 72 + ks * 16 + k_add)) * 2;
                uint32_t bh4[4], bl4[4];
                ldsm_x4(bh4[0], bh4[1], bh4[2], bh4[3], sb + kb + koff);
                ldsm_x4(bl4[0], bl4[1], bl4[2], bl4[3], sb + kb + 9216 + koff);
                mma16816(s[2 * np],     qhf, bh4);
                mma16816(s[2 * np],     qhf, bl4);
                mma16816(s[2 * np],     qlf, bh4);
                mma16816(s[2 * np + 1], qhf, bh4 + 2);
                mma16816(s[2 * np + 1], qhf, bl4 + 2);
                mma16816(s[2 * np + 1], qlf, bh4 + 2);
            }
        }
#pragma unroll
        for (int nb = 0; nb < 8; nb++) {
            const int col = kt * 64 + nb * 8 + 2 * tig;
            const float mc0 = maskb[col], mc1 = maskb[col + 1];
            s[nb][0] = s[nb][0] * SC2 + mc0;
            s[nb][1] = s[nb][1] * SC2 + mc1;
            s[nb][2] = s[nb][2] * SC2 + mc0;
            s[nb][3] = s[nb][3] * SC2 + mc1;
        }

        float t0 = -1e30f, t1 = -1e30f;
#pragma unroll
        for (int nb = 0; nb < 8; nb++) {
            t0 = fmaxf(t0, fmaxf(s[nb][0], s[nb][1]));
            t1 = fmaxf(t1, fmaxf(s[nb][2], s[nb][3]));
        }
        t0 = fmaxf(t0, __shfl_xor_sync(0xffffffffu, t0, 1));
        t0 = fmaxf(t0, __shfl_xor_sync(0xffffffffu, t0, 2));
        t1 = fmaxf(t1, __shfl_xor_sync(0xffffffffu, t1, 1));
        t1 = fmaxf(t1, __shfl_xor_sync(0xffffffffu, t1, 2));
        const float mn0 = fmaxf(m0, t0), mn1 = fmaxf(m1, t1);
        const float f0 = fexp2(m0 - mn0), f1 = fexp2(m1 - mn1);
        m0 = mn0; m1 = mn1;
        float ls0 = 0.f, ls1 = 0.f;
#pragma unroll
        for (int nb = 0; nb < 8; nb++) {
            s[nb][0] = fexp2(s[nb][0] - mn0);
            s[nb][1] = fexp2(s[nb][1] - mn0);
            s[nb][2] = fexp2(s[nb][2] - mn1);
            s[nb][3] = fexp2(s[nb][3] - mn1);
            ls0 += s[nb][0] + s[nb][1];
            ls1 += s[nb][2] + s[nb][3];
        }
        ls0 += __shfl_xor_sync(0xffffffffu, ls0, 1);
        ls0 += __shfl_xor_sync(0xffffffffu, ls0, 2);
        ls1 += __shfl_xor_sync(0xffffffffu, ls1, 1);
        ls1 += __shfl_xor_sync(0xffffffffu, ls1, 2);
        l0 = l0 * f0 + ls0;
        l1 = l1 * f1 + ls1;
#pragma unroll
        for (int nb = 0; nb < 8; nb++) {
            o[nb][0] *= f0; o[nb][1] *= f0;
            o[nb][2] *= f1; o[nb][3] *= f1;
        }

#pragma unroll
        for (int ks = 0; ks < 4; ks++) {
            uint32_t ph[4], pl[4];
            pack_split2(s[2 * ks][0],     s[2 * ks][1],     ph[0], pl[0]);
            pack_split2(s[2 * ks][2],     s[2 * ks][3],     ph[1], pl[1]);
            pack_split2(s[2 * ks + 1][0], s[2 * ks + 1][1], ph[2], pl[2]);
            pack_split2(s[2 * ks + 1][2], s[2 * ks + 1][3], ph[3], pl[3]);
#pragma unroll
            for (int np = 0; np < 4; np++) {
                uint32_t voff = ((uint32_t)((ks * 16 + (lane & 15)) * 72
                                + np * 16 + ((lane >> 4) & 1) * 8)) * 2;
                uint32_t vb4h[4], vb4l[4];
                ldsm_x4t(vb4h[0], vb4h[1], vb4h[2], vb4h[3], sb + vb + voff);
                ldsm_x4t(vb4l[0], vb4l[1], vb4l[2], vb4l[3], sb + vb + 9216 + voff);
                mma16816(o[2 * np],     ph, vb4h);
                mma16816(o[2 * np],     ph, vb4l);
                mma16816(o[2 * np],     pl, vb4h);
                mma16816(o[2 * np + 1], ph, vb4h + 2);
                mma16816(o[2 * np + 1], ph, vb4l + 2);
                mma16816(o[2 * np + 1], pl, vb4h + 2);
            }
        }
    }

    {
        const int r0 = wid * 16 + gid;
        const float inv0 = 1.0f / l0, inv1 = 1.0f / l1;
#pragma unroll
        for (int nb = 0; nb < 8; nb++) {
            const int col = h * DHn + nb * 8 + 2 * tig;
            uint32_t hA, lA, hB, lB;
            pack_split2(o[nb][0] * inv0, o[nb][1] * inv0, hA, lA);
            pack_split2(o[nb][2] * inv1, o[nb][3] * inv1, hB, lB);
            size_t off0 = (rowbase + r0) * Dn + col;
            size_t off1 = (rowbase + r0 + 8) * Dn + col;
            *(uint32_t*)((char*)ctxh + off0 * 2) = hA;
            *(uint32_t*)((char*)ctxl + off0 * 2) = lA;
            *(uint32_t*)((char*)ctxh + off1 * 2) = hB;
            *(uint32_t*)((char*)ctxl + off1 * 2) = lB;
        }
    }
}

// ---------------- host orchestration ----------------
extern "C" void kernel_launch(void* const* d_in, const int* in_sizes, int n_in,
                              void* d_out, int out_size)
{
    const float* video    = (const float*)d_in[0];
    const float* question = (const float*)d_in[1];
    const int*   mask     = (const int*)  d_in[2];
    const float* pos_emb  = (const float*)d_in[3];
    const float* mod_emb  = (const float*)d_in[4];
    const float* Wv       = (const float*)d_in[5];
    const float* bv       = (const float*)d_in[6];
    const float* nv_g     = (const float*)d_in[7];
    const float* nv_b     = (const float*)d_in[8];
    const float* emb_g    = (const float*)d_in[9];
    const float* emb_b    = (const float*)d_in[10];
    const float* Wq       = (const float*)d_in[11];
    const float* bq       = (const float*)d_in[12];
    const float* Wk       = (const float*)d_in[13];
    const float* bk       = (const float*)d_in[14];
    const float* Wva      = (const float*)d_in[15];
    const float* bva      = (const float*)d_in[16];
    const float* Wo       = (const float*)d_in[17];
    const float* bo       = (const float*)d_in[18];
    const float* ln1_g    = (const float*)d_in[19];
    const float* ln1_b    = (const float*)d_in[20];
    const float* W1       = (const float*)d_in[21];
    const float* b1       = (const float*)d_in[22];
    const float* W2       = (const float*)d_in[23];
    const float* b2       = (const float*)d_in[24];
    const float* ln2_g    = (const float*)d_in[25];
    const float* ln2_b    = (const float*)d_in[26];

    float *x, *t1;
    __nv_bfloat16 *xh, *xl, *aqh, *aql, *akh, *akl, *avh, *avl;
    __nv_bfloat16 *ch, *cl, *hh, *hl, *vh, *vl;
    __nv_bfloat16 *wvh, *wvl, *wqkvh, *wqkvl, *woh, *wol, *w1h, *w1l, *w2h, *w2l;
    cudaGetSymbolAddress((void**)&x,   g_x);
    cudaGetSymbolAddress((void**)&t1,  g_t1);
    cudaGetSymbolAddress((void**)&xh,  g_xh);  cudaGetSymbolAddress((void**)&xl,  g_xl);
    cudaGetSymbolAddress((void**)&aqh, g_aqh); cudaGetSymbolAddress((void**)&aql, g_aql);
    cudaGetSymbolAddress((void**)&akh, g_akh); cudaGetSymbolAddress((void**)&akl, g_akl);
    cudaGetSymbolAddress((void**)&avh, g_avh); cudaGetSymbolAddress((void**)&avl, g_avl);
    cudaGetSymbolAddress((void**)&ch,  g_ch);  cudaGetSymbolAddress((void**)&cl,  g_cl);
    cudaGetSymbolAddress((void**)&hh,  g_hh);  cudaGetSymbolAddress((void**)&hl,  g_hl);
    cudaGetSymbolAddress((void**)&vh,  g_vh);  cudaGetSymbolAddress((void**)&vl,  g_vl);
    cudaGetSymbolAddress((void**)&wvh,   g_wvh);   cudaGetSymbolAddress((void**)&wvl,   g_wvl);
    cudaGetSymbolAddress((void**)&wqkvh, g_wqkvh); cudaGetSymbolAddress((void**)&wqkvl, g_wqkvl);
    cudaGetSymbolAddress((void**)&woh,   g_woh);   cudaGetSymbolAddress((void**)&wol,   g_wol);
    cudaGetSymbolAddress((void**)&w1h,   g_w1h);   cudaGetSymbolAddress((void**)&w1l,   g_w1l);
    cudaGetSymbolAddress((void**)&w2h,   g_w2h);   cudaGetSymbolAddress((void**)&w2l,   g_w2l);

    static cudaStream_t s1 = nullptr;
    static cudaEvent_t evFork = nullptr, evWv = nullptr, evW = nullptr;
    static bool attr_set = false;
    if (!attr_set) {
        cudaFuncSetAttribute(attn_kernel, cudaFuncAttributeMaxDynamicSharedMemorySize, AT_TOTAL);
        cudaFuncSetAttribute(gemm_bf<0,1>, cudaFuncAttributeMaxDynamicSharedMemorySize, SM_TOTAL);
        cudaFuncSetAttribute(gemm_bf<1,2>, cudaFuncAttributeMaxDynamicSharedMemorySize, SM_TOTAL);
        cudaFuncSetAttribute(gemm_bf<2,1>, cudaFuncAttributeMaxDynamicSharedMemorySize, SM_TOTAL);
        cudaFuncSetAttribute(gemm_qkv, cudaFuncAttributeMaxDynamicSharedMemorySize, SM_TOTAL);
        cudaStreamCreateWithFlags(&s1, cudaStreamNonBlocking);
        cudaEventCreateWithFlags(&evFork, cudaEventDisableTiming);
        cudaEventCreateWithFlags(&evWv, cudaEventDisableTiming);
        cudaEventCreateWithFlags(&evW, cudaEventDisableTiming);
        attr_set = true;
    }

    // ---- fork side stream: weight splits concurrent with video path ----
    cudaEventRecord(evFork, 0);
    cudaStreamWaitEvent(s1, evFork, 0);
    split_kernel<<<(FDn * Dn) / 1024, 256, 0, s1>>>(Wv, wvh, wvl);
    cudaEventRecord(evWv, s1);
    for (int i = 0; i < NLn; i++) {
        const size_t wD = (size_t)i * Dn * Dn;
        const size_t qD = (size_t)i * 3 * Dn * Dn;
        split_kernel<<<(Dn * Dn) / 1024, 256, 0, s1>>>(Wq  + wD, wqkvh + qD,               wqkvl + qD);
        split_kernel<<<(Dn * Dn) / 1024, 256, 0, s1>>>(Wk  + wD, wqkvh + qD + Dn * Dn,     wqkvl + qD + Dn * Dn);
        split_kernel<<<(Dn * Dn) / 1024, 256, 0, s1>>>(Wva + wD, wqkvh + qD + 2 * Dn * Dn, wqkvl + qD + 2 * Dn * Dn);
        split_kernel<<<(Dn * Dn) / 1024, 256, 0, s1>>>(Wo + wD, woh + wD, wol + wD);
        split_kernel<<<(Dn * FFn) / 1024, 256, 0, s1>>>(W1 + (size_t)i * Dn * FFn,
                                                        w1h + (size_t)i * Dn * FFn,
                                                        w1l + (size_t)i * Dn * FFn);
        split_kernel<<<(FFn * Dn) / 1024, 256, 0, s1>>>(W2 + (size_t)i * FFn * Dn,
                                                        w2h + (size_t)i * FFn * Dn,
                                                        w2l + (size_t)i * FFn * Dn);
    }
    cudaEventRecord(evW, s1);

    // ---- main stream: video path ----
    split_kernel<<<(BTr * FDn) / 1024, 256>>>(video, vh, vl);
    cudaStreamWaitEvent(0, evWv, 0);
    gemm_bf<0,1><<<dim3(Dn / 128, BTr / 128), 256, SM_TOTAL>>>(
        vh, vl, wvh, wvl, bv, nullptr, t1, nullptr, nullptr, BTr, Dn, FDn);
    ln_kernel<<<BTr / 8, 256>>>(t1, nv_g, nv_b, x, xh, xl, 1);
    embed_ln_kernel<<<BSr / 8, 256>>>(question, pos_emb, mod_emb, emb_g, emb_b, x, xh, xl);
    cudaStreamWaitEvent(0, evW, 0);

    for (int i = 0; i < NLn; i++) {
        const size_t wD = (size_t)i * Dn * Dn;
        const size_t qD = (size_t)i * 3 * Dn * Dn;
        gemm_qkv<<<dim3(12, BSr / 128), 256, SM_TOTAL>>>(
            xh, xl, wqkvh + qD, wqkvl + qD, bq + i * Dn, bk + i * Dn, bva + i * Dn,
            aqh, aql, akh, akl, avh, avl);

        attn_kernel<<<dim3(Sn / 128, Bn * Hn), 256, AT_TOTAL>>>(
            aqh, aql, akh, akl, avh, avl, mask, ch, cl);

        gemm_bf<2,1><<<dim3(Dn / 128, BSr / 128), 256, SM_TOTAL>>>(
            ch, cl, woh + wD, wol + wD, bo + i * Dn, x, t1, nullptr, nullptr, BSr, Dn, Dn);
        ln_kernel<<<BSr / 8, 256>>>(t1, ln1_g + i * Dn, ln1_b + i * Dn, x, xh, xl, 2);

        gemm_bf<1,2><<<dim3(FFn / 128, BSr / 128), 256, SM_TOTAL>>>(
            xh, xl, w1h + (size_t)i * Dn * FFn, w1l + (size_t)i * Dn * FFn,
            b1 + i * FFn, nullptr, nullptr, hh, hl, BSr, FFn, Dn);
        gemm_bf<2,1><<<dim3(Dn / 128, BSr / 128), 256, SM_TOTAL>>>(
            hh, hl, w2h + (size_t)i * FFn * Dn, w2l + (size_t)i * FFn * Dn,
            b2 + i * Dn, x, t1, nullptr, nullptr, BSr, Dn, FFn);

        if (i == NLn - 1) {
            ln_kernel<<<BSr / 8, 256>>>(t1, ln2_g + i * Dn, ln2_b + i * Dn,
                                        (float*)d_out, xh, xl, 0);
        } else {
            ln_kernel<<<BSr / 8, 256>>>(t1, ln2_g + i * Dn, ln2_b + i * Dn, x, xh, xl, 2);
        }
    }
}